// round 1
// baseline (speedup 1.0000x reference)
#include <cuda_runtime.h>
#include <cuda_bf16.h>
#include <cstddef>

// VAE forward: scalar ELBO
// B=65536, D=512, H=1024, L=64
#define BATCH 65536
#define DIN   512
#define HID   1024
#define LAT   64
#define LOG2PI 1.8378770664093453f

// ---------------- scratch (allocation-free rule: __device__ globals) --------
__device__ float sc_h[(size_t)BATCH * HID];      // h, later reused as hd (256MB)
__device__ float sc_z[(size_t)BATCH * LAT];      // 16MB
__device__ float sc_kl[BATCH];
__device__ float sc_logits[(size_t)BATCH * DIN]; // 128MB
__device__ float sc_lvx[(size_t)BATCH * DIN];    // 128MB
__device__ float sc_row[BATCH];
__device__ float sc_part[256];

// ---------------- generic fp32 GEMM: C = act(A[M,K] @ W[K,N] + bias) --------
// 128x128 block tile, BK=16, 256 threads, 8x8 per-thread microtile.
template<int ACT>
__global__ void gemm128(const float* __restrict__ A, const float* __restrict__ W,
                        const float* __restrict__ bias, float* __restrict__ C,
                        int M, int N, int K) {
    __shared__ float As[128][17];
    __shared__ float Bs[16][128];
    const int tid = threadIdx.x;
    const int tx = tid & 15, ty = tid >> 4;
    const int row0 = blockIdx.y * 128, col0 = blockIdx.x * 128;

    float acc[8][8];
#pragma unroll
    for (int i = 0; i < 8; i++)
#pragma unroll
        for (int j = 0; j < 8; j++) acc[i][j] = 0.0f;

    for (int k0 = 0; k0 < K; k0 += 16) {
        // load A tile: 128 rows x 16 cols (512 float4, 2 per thread)
#pragma unroll
        for (int u = 0; u < 2; u++) {
            int v = tid + u * 256;
            int r = v >> 2, c = (v & 3) << 2;
            float4 t = *(const float4*)(A + (size_t)(row0 + r) * K + k0 + c);
            As[r][c + 0] = t.x; As[r][c + 1] = t.y;
            As[r][c + 2] = t.z; As[r][c + 3] = t.w;
        }
        // load W tile: 16 rows x 128 cols
#pragma unroll
        for (int u = 0; u < 2; u++) {
            int v = tid + u * 256;
            int r = v >> 5, c = (v & 31) << 2;
            *(float4*)&Bs[r][c] = *(const float4*)(W + (size_t)(k0 + r) * N + col0 + c);
        }
        __syncthreads();
#pragma unroll
        for (int kk = 0; kk < 16; kk++) {
            float ra[8], rb[8];
#pragma unroll
            for (int i = 0; i < 8; i++) ra[i] = As[ty * 8 + i][kk];
            float4 b0 = *(float4*)&Bs[kk][tx * 8];
            float4 b1 = *(float4*)&Bs[kk][tx * 8 + 4];
            rb[0] = b0.x; rb[1] = b0.y; rb[2] = b0.z; rb[3] = b0.w;
            rb[4] = b1.x; rb[5] = b1.y; rb[6] = b1.z; rb[7] = b1.w;
#pragma unroll
            for (int i = 0; i < 8; i++)
#pragma unroll
                for (int j = 0; j < 8; j++) acc[i][j] += ra[i] * rb[j];
        }
        __syncthreads();
    }
    // epilogue
#pragma unroll
    for (int i = 0; i < 8; i++) {
        int r = row0 + ty * 8 + i;
#pragma unroll
        for (int j0 = 0; j0 < 8; j0 += 4) {
            int c = col0 + tx * 8 + j0;
            float4 o;
            o.x = acc[i][j0 + 0] + bias[c + 0];
            o.y = acc[i][j0 + 1] + bias[c + 1];
            o.z = acc[i][j0 + 2] + bias[c + 2];
            o.w = acc[i][j0 + 3] + bias[c + 3];
            if (ACT) { o.x = tanhf(o.x); o.y = tanhf(o.y); o.z = tanhf(o.z); o.w = tanhf(o.w); }
            *(float4*)(C + (size_t)r * N + c) = o;
        }
    }
}

// ---------------- encoder head: mu_z, lv_z -> z, KL -------------------------
// Each block: 64 rows x full 64 cols, K=1024. 256 threads, 4x4 microtile x2 mats.
__global__ void enc_head(const float* __restrict__ h,
                         const float* __restrict__ Wmu, const float* __restrict__ bmu,
                         const float* __restrict__ Wlv, const float* __restrict__ blv,
                         const float* __restrict__ eps,
                         float* __restrict__ z, float* __restrict__ kl) {
    __shared__ float Hs[64][17];
    __shared__ float Wm[16][64];
    __shared__ float Wl[16][64];
    __shared__ float red[64][17];
    const int tid = threadIdx.x;
    const int tx = tid & 15, ty = tid >> 4;
    const int row0 = blockIdx.x * 64;

    float am[4][4], al[4][4];
#pragma unroll
    for (int i = 0; i < 4; i++)
#pragma unroll
        for (int j = 0; j < 4; j++) { am[i][j] = 0.0f; al[i][j] = 0.0f; }

    for (int k0 = 0; k0 < HID; k0 += 16) {
        {
            int r = tid >> 2, c = (tid & 3) << 2;
            float4 t = *(const float4*)(h + (size_t)(row0 + r) * HID + k0 + c);
            Hs[r][c + 0] = t.x; Hs[r][c + 1] = t.y; Hs[r][c + 2] = t.z; Hs[r][c + 3] = t.w;
            int wr = tid >> 4, wc = (tid & 15) << 2;
            *(float4*)&Wm[wr][wc] = *(const float4*)(Wmu + (size_t)(k0 + wr) * LAT + wc);
            *(float4*)&Wl[wr][wc] = *(const float4*)(Wlv + (size_t)(k0 + wr) * LAT + wc);
        }
        __syncthreads();
#pragma unroll
        for (int kk = 0; kk < 16; kk++) {
            float ha[4], wm[4], wl[4];
#pragma unroll
            for (int i = 0; i < 4; i++) ha[i] = Hs[ty * 4 + i][kk];
#pragma unroll
            for (int j = 0; j < 4; j++) { wm[j] = Wm[kk][tx * 4 + j]; wl[j] = Wl[kk][tx * 4 + j]; }
#pragma unroll
            for (int i = 0; i < 4; i++)
#pragma unroll
                for (int j = 0; j < 4; j++) {
                    am[i][j] += ha[i] * wm[j];
                    al[i][j] += ha[i] * wl[j];
                }
        }
        __syncthreads();
    }
    // epilogue: z = mu + exp(0.5 lv)*eps ; kl row-sum
    float klp[4];
#pragma unroll
    for (int i = 0; i < 4; i++) {
        int r = row0 + ty * 4 + i;
        int c0 = tx * 4;
        float4 ev = *(const float4*)(eps + (size_t)r * LAT + c0);
        float ee[4] = { ev.x, ev.y, ev.z, ev.w };
        float zo[4];
        float s = 0.0f;
#pragma unroll
        for (int j = 0; j < 4; j++) {
            float mu = am[i][j] + bmu[c0 + j];
            float lv = al[i][j] + blv[c0 + j];
            zo[j] = mu + expf(0.5f * lv) * ee[j];
            s += 1.0f + lv - mu * mu - expf(lv);
        }
        float4 zv = make_float4(zo[0], zo[1], zo[2], zo[3]);
        *(float4*)(z + (size_t)r * LAT + c0) = zv;
        klp[i] = s;
    }
#pragma unroll
    for (int i = 0; i < 4; i++) red[ty * 4 + i][tx] = klp[i];
    __syncthreads();
    if (tid < 64) {
        float s = 0.0f;
#pragma unroll
        for (int j = 0; j < 16; j++) s += red[tid][j];
        kl[row0 + tid] = -0.5f * s;
    }
}

// ---------------- per-row softmax + diag-Gaussian log-likelihood ------------
__global__ void row_loss(const float* __restrict__ logits, const float* __restrict__ lvx,
                         const float* __restrict__ x, const float* __restrict__ kl,
                         float* __restrict__ rowout) {
    const int row = blockIdx.x;
    const int t = threadIdx.x;
    __shared__ float sh[8];
    const float* lr = logits + (size_t)row * DIN;
    float l0 = lr[t], l1 = lr[t + 256];

    // max over 512
    float m = fmaxf(l0, l1);
#pragma unroll
    for (int o = 16; o > 0; o >>= 1) m = fmaxf(m, __shfl_xor_sync(0xffffffffu, m, o));
    if ((t & 31) == 0) sh[t >> 5] = m;
    __syncthreads();
    m = sh[0];
#pragma unroll
    for (int w = 1; w < 8; w++) m = fmaxf(m, sh[w]);
    __syncthreads();

    // sum(exp)
    float e0 = expf(l0 - m), e1 = expf(l1 - m);
    float s = e0 + e1;
#pragma unroll
    for (int o = 16; o > 0; o >>= 1) s += __shfl_xor_sync(0xffffffffu, s, o);
    if ((t & 31) == 0) sh[t >> 5] = s;
    __syncthreads();
    s = 0.0f;
#pragma unroll
    for (int w = 0; w < 8; w++) s += sh[w];
    __syncthreads();
    float inv = 1.0f / s;

    const float* xr = x + (size_t)row * DIN;
    const float* vr = lvx + (size_t)row * DIN;
    float acc = 0.0f;
    {
        float p = e0 * inv, xv = xr[t], lv = vr[t];
        float d = xv - p;
        acc += lv + d * d * expf(-lv);
        p = e1 * inv; xv = xr[t + 256]; lv = vr[t + 256];
        d = xv - p;
        acc += lv + d * d * expf(-lv);
    }
#pragma unroll
    for (int o = 16; o > 0; o >>= 1) acc += __shfl_xor_sync(0xffffffffu, acc, o);
    if ((t & 31) == 0) sh[t >> 5] = acc;
    __syncthreads();
    if (t == 0) {
        float tot = 0.0f;
#pragma unroll
        for (int w = 0; w < 8; w++) tot += sh[w];
        float ln_pxz = -0.5f * (tot + (float)DIN * LOG2PI);
        rowout[row] = ln_pxz - kl[row];
    }
}

// ---------------- deterministic two-stage mean reduction --------------------
__global__ void reduce_partial(const float* __restrict__ in, float* __restrict__ part) {
    const int t = threadIdx.x;
    __shared__ float sh[8];
    float v = in[blockIdx.x * 256 + t];
#pragma unroll
    for (int o = 16; o > 0; o >>= 1) v += __shfl_xor_sync(0xffffffffu, v, o);
    if ((t & 31) == 0) sh[t >> 5] = v;
    __syncthreads();
    if (t == 0) {
        float s = 0.0f;
#pragma unroll
        for (int w = 0; w < 8; w++) s += sh[w];
        part[blockIdx.x] = s;
    }
}

__global__ void reduce_final(const float* __restrict__ part, float* __restrict__ out) {
    const int t = threadIdx.x;
    __shared__ float sh[8];
    float v = part[t];
#pragma unroll
    for (int o = 16; o > 0; o >>= 1) v += __shfl_xor_sync(0xffffffffu, v, o);
    if ((t & 31) == 0) sh[t >> 5] = v;
    __syncthreads();
    if (t == 0) {
        float s = 0.0f;
#pragma unroll
        for (int w = 0; w < 8; w++) s += sh[w];
        out[0] = s * (1.0f / (float)BATCH);
    }
}

// ---------------- launch ----------------------------------------------------
extern "C" void kernel_launch(void* const* d_in, const int* in_sizes, int n_in,
                              void* d_out, int out_size) {
    const float* x        = (const float*)d_in[0];
    const float* eps      = (const float*)d_in[1];
    const float* W_enc_h  = (const float*)d_in[2];
    const float* b_enc_h  = (const float*)d_in[3];
    const float* W_enc_mu = (const float*)d_in[4];
    const float* b_enc_mu = (const float*)d_in[5];
    const float* W_enc_lv = (const float*)d_in[6];
    const float* b_enc_lv = (const float*)d_in[7];
    const float* W_dec_h  = (const float*)d_in[8];
    const float* b_dec_h  = (const float*)d_in[9];
    const float* W_dec_mu = (const float*)d_in[10];
    const float* b_dec_mu = (const float*)d_in[11];
    const float* W_dec_lv = (const float*)d_in[12];
    const float* b_dec_lv = (const float*)d_in[13];
    float* out = (float*)d_out;

    float *p_h, *p_z, *p_kl, *p_logits, *p_lvx, *p_row, *p_part;
    cudaGetSymbolAddress((void**)&p_h, sc_h);
    cudaGetSymbolAddress((void**)&p_z, sc_z);
    cudaGetSymbolAddress((void**)&p_kl, sc_kl);
    cudaGetSymbolAddress((void**)&p_logits, sc_logits);
    cudaGetSymbolAddress((void**)&p_lvx, sc_lvx);
    cudaGetSymbolAddress((void**)&p_row, sc_row);
    cudaGetSymbolAddress((void**)&p_part, sc_part);

    // 1) h = tanh(x @ W_enc_h + b)   [B,H]
    gemm128<1><<<dim3(HID / 128, BATCH / 128), 256>>>(x, W_enc_h, b_enc_h, p_h, BATCH, HID, DIN);
    // 2) mu_z / lv_z -> z, kl
    enc_head<<<BATCH / 64, 256>>>(p_h, W_enc_mu, b_enc_mu, W_enc_lv, b_enc_lv, eps, p_z, p_kl);
    // 3) hd = tanh(z @ W_dec_h + b)  (reuse p_h)
    gemm128<1><<<dim3(HID / 128, BATCH / 128), 256>>>(p_z, W_dec_h, b_dec_h, p_h, BATCH, HID, LAT);
    // 4) logits = hd @ W_dec_mu + b ; lvx = hd @ W_dec_lv + b
    gemm128<0><<<dim3(DIN / 128, BATCH / 128), 256>>>(p_h, W_dec_mu, b_dec_mu, p_logits, BATCH, DIN, HID);
    gemm128<0><<<dim3(DIN / 128, BATCH / 128), 256>>>(p_h, W_dec_lv, b_dec_lv, p_lvx, BATCH, DIN, HID);
    // 5) per-row softmax + likelihood - kl
    row_loss<<<BATCH, 256>>>(p_logits, p_lvx, x, p_kl, p_row);
    // 6) deterministic mean
    reduce_partial<<<256, 256>>>(p_row, p_part);
    reduce_final<<<1, 256>>>(p_part, out);
}

// round 7
// speedup vs baseline: 5.9794x; 5.9794x over previous
#include <cuda_runtime.h>
#include <cuda_bf16.h>
#include <cstdint>
#include <cstddef>

#define BATCH 65536
#define DIN   512
#define HID   1024
#define LAT   64
#define LOG2PI 1.8378770664093453f

typedef __nv_bfloat16 bf16;

// ---------------- scratch (__device__ globals; allocation-free rule) --------
__device__ bf16  sc_xb[(size_t)BATCH * DIN];        // x bf16             64MB
__device__ bf16  sc_h [(size_t)BATCH * HID];        // h / hd bf16       128MB
__device__ bf16  sc_z [(size_t)BATCH * LAT];        // z bf16              8MB
__device__ float sc_out4[(size_t)BATCH * (2*DIN)];  // logits|lvx fp32   256MB
__device__ float sc_kl[BATCH];
__device__ float sc_row[BATCH];
__device__ float sc_part[256];
__device__ bf16  sc_Wt1[(size_t)HID * DIN];
__device__ bf16  sc_Wt2[(size_t)(2*LAT) * HID];
__device__ bf16  sc_Wt3[(size_t)HID * LAT];
__device__ bf16  sc_Wt4[(size_t)(2*DIN) * HID];
__device__ float sc_b2[2*LAT];
__device__ float sc_b4[2*DIN];

// ---------------- helpers ---------------------------------------------------
__device__ __forceinline__ uint32_t smem_u32(const void* p) {
    uint32_t a;
    asm("{ .reg .u64 t; cvta.to.shared.u64 t, %1; cvt.u32.u64 %0, t; }" : "=r"(a) : "l"(p));
    return a;
}
#define SWZ(off) ((off) ^ (((off) >> 3) & 0x70))

__device__ __forceinline__ void cp16(uint32_t dst, const void* src) {
    asm volatile("cp.async.cg.shared.global [%0], [%1], 16;" :: "r"(dst), "l"(src));
}
#define CP_COMMIT() asm volatile("cp.async.commit_group;" ::: "memory")
#define CP_WAIT(n)  asm volatile("cp.async.wait_group %0;" :: "n"(n) : "memory")

__device__ __forceinline__ void ldmA(uint32_t& a0, uint32_t& a1, uint32_t& a2, uint32_t& a3,
                                     uint32_t addr) {
    asm volatile("ldmatrix.sync.aligned.m8n8.x4.shared.b16 {%0,%1,%2,%3}, [%4];"
                 : "=r"(a0), "=r"(a1), "=r"(a2), "=r"(a3) : "r"(addr));
}
__device__ __forceinline__ void ldmB(uint32_t& b0, uint32_t& b1, uint32_t addr) {
    asm volatile("ldmatrix.sync.aligned.m8n8.x2.shared.b16 {%0,%1}, [%2];"
                 : "=r"(b0), "=r"(b1) : "r"(addr));
}
__device__ __forceinline__ void mma16816(float& c0, float& c1, float& c2, float& c3,
                                         uint32_t a0, uint32_t a1, uint32_t a2, uint32_t a3,
                                         uint32_t b0, uint32_t b1) {
    asm volatile("mma.sync.aligned.m16n8k16.row.col.f32.bf16.bf16.f32 "
                 "{%0,%1,%2,%3}, {%4,%5,%6,%7}, {%8,%9}, {%0,%1,%2,%3};"
                 : "+f"(c0), "+f"(c1), "+f"(c2), "+f"(c3)
                 : "r"(a0), "r"(a1), "r"(a2), "r"(a3), "r"(b0), "r"(b1));
}

// ---------------- tile prefetch: 128 rows x 64 bf16, SW128, cp.async --------
__device__ __forceinline__ void prefetch_tile(const bf16* __restrict__ g, int pitch,
                                              int row0, int kofs, uint32_t sbase, int tid) {
#pragma unroll
    for (int u = 0; u < 4; u++) {
        int id  = tid + u * 256;
        int r   = id >> 3;
        int c16 = id & 7;
        uint32_t off = (uint32_t)(r * 128 + c16 * 16);
        cp16(sbase + SWZ(off), g + (size_t)(row0 + r) * pitch + kofs + c16 * 8);
    }
}

// ---------------- mma.sync GEMM: D = A[M,K] @ Bt[N,K]^T ---------------------
// block tile 128x128, BK=64, 256 threads (8 warps, 2x4), warp tile 64x32.
// EPI: 0 = bias+fp32 store, 1 = bias+tanh+bf16 store, 2 = enc head (z, KL)
static constexpr int PAD = 130;
static constexpr int SMEMSZ = PAD * 128 * 4;   // 66560 >= 4*16384 tile bytes

template<int EPI>
__global__ __launch_bounds__(256) void gemm_mma(
    const bf16* __restrict__ A, int Ka,
    const bf16* __restrict__ Bt,
    const float* __restrict__ bias,
    void* __restrict__ Cout, int Np,
    const float* __restrict__ eps, bf16* __restrict__ zout, float* __restrict__ klout)
{
    extern __shared__ char smem[];
    const uint32_t sb = smem_u32(smem);
    const int tid = threadIdx.x, wid = tid >> 5, lane = tid & 31;
    const int wm = wid >> 2, wn = wid & 3;           // warp grid 2 x 4
    const int row0 = blockIdx.y * 128, col0 = blockIdx.x * 128;
    const uint32_t SA[2] = { sb, sb + 16384 };
    const uint32_t SB[2] = { sb + 32768, sb + 49152 };

    float c[4][4][4];
#pragma unroll
    for (int i = 0; i < 4; i++)
#pragma unroll
        for (int j = 0; j < 4; j++)
#pragma unroll
            for (int q = 0; q < 4; q++) c[i][j][q] = 0.0f;

    const int KT = Ka / 64;
    prefetch_tile(A,  Ka, row0, 0, SA[0], tid);
    prefetch_tile(Bt, Ka, col0, 0, SB[0], tid);
    CP_COMMIT();

    // per-thread ldmatrix address components (within tile)
    const int arow = wm * 64 + (lane & 15);
    const uint32_t acol = ((uint32_t)(lane >> 4)) << 4;
    const int brow = wn * 32 + (lane & 7);
    const uint32_t bcol = ((uint32_t)((lane >> 3) & 1)) << 4;

    for (int kt = 0; kt < KT; kt++) {
        const int buf = kt & 1;
        if (kt + 1 < KT) {
            prefetch_tile(A,  Ka, row0, (kt + 1) * 64, SA[buf ^ 1], tid);
            prefetch_tile(Bt, Ka, col0, (kt + 1) * 64, SB[buf ^ 1], tid);
            CP_COMMIT();
            CP_WAIT(1);
        } else {
            CP_WAIT(0);
        }
        __syncthreads();

#pragma unroll
        for (int ks = 0; ks < 4; ks++) {
            uint32_t af[4][4], bfr[4][2];
#pragma unroll
            for (int i = 0; i < 4; i++) {
                uint32_t off = (uint32_t)((arow + i * 16) * 128) + ks * 32 + acol;
                ldmA(af[i][0], af[i][1], af[i][2], af[i][3], SA[buf] + SWZ(off));
            }
#pragma unroll
            for (int j = 0; j < 4; j++) {
                uint32_t off = (uint32_t)((brow + j * 8) * 128) + ks * 32 + bcol;
                ldmB(bfr[j][0], bfr[j][1], SB[buf] + SWZ(off));
            }
#pragma unroll
            for (int i = 0; i < 4; i++)
#pragma unroll
                for (int j = 0; j < 4; j++)
                    mma16816(c[i][j][0], c[i][j][1], c[i][j][2], c[i][j][3],
                             af[i][0], af[i][1], af[i][2], af[i][3],
                             bfr[j][0], bfr[j][1]);
        }
        __syncthreads();
    }

    // ---- stage accumulators to padded smem ----
    float* stg = (float*)smem;
    {
        const int r0 = wm * 64 + (lane >> 2);
        const int cfix = wn * 32 + (lane & 3) * 2;
#pragma unroll
        for (int i = 0; i < 4; i++)
#pragma unroll
            for (int j = 0; j < 4; j++) {
                int sr = r0 + i * 16, scol = cfix + j * 8;
                stg[sr * PAD + scol]           = c[i][j][0];
                stg[sr * PAD + scol + 1]       = c[i][j][1];
                stg[(sr + 8) * PAD + scol]     = c[i][j][2];
                stg[(sr + 8) * PAD + scol + 1] = c[i][j][3];
            }
    }
    __syncthreads();

    if (EPI == 2) {
        if (tid < 128) {
            const int row = tid;
            const int r = row0 + row;
            float klacc = 0.0f;
            uint32_t zp[32];
            const float* er = eps + (size_t)r * LAT;
#pragma unroll
            for (int j = 0; j < 64; j += 2) {
                float mu0 = stg[row * PAD + j]     + bias[j];
                float mu1 = stg[row * PAD + j + 1] + bias[j + 1];
                float lv0 = stg[row * PAD + 64 + j]     + bias[64 + j];
                float lv1 = stg[row * PAD + 64 + j + 1] + bias[64 + j + 1];
                float z0 = fmaf(expf(0.5f * lv0), er[j],     mu0);
                float z1 = fmaf(expf(0.5f * lv1), er[j + 1], mu1);
                klacc += (1.0f + lv0 - mu0 * mu0 - expf(lv0));
                klacc += (1.0f + lv1 - mu1 * mu1 - expf(lv1));
                __nv_bfloat162 t = __floats2bfloat162_rn(z0, z1);
                zp[j >> 1] = *(uint32_t*)&t;
            }
            uint4* dst = (uint4*)(zout + (size_t)r * LAT);
#pragma unroll
            for (int q = 0; q < 8; q++) dst[q] = ((uint4*)zp)[q];
            klout[r] = -0.5f * klacc;
        }
    } else {
#pragma unroll
        for (int it = 0; it < 16; it++) {
            int id = tid + it * 256;
            int row = id >> 5, col = (id & 31) * 4;
            float v0 = stg[row * PAD + col]     + bias[col0 + col];
            float v1 = stg[row * PAD + col + 1] + bias[col0 + col + 1];
            float v2 = stg[row * PAD + col + 2] + bias[col0 + col + 2];
            float v3 = stg[row * PAD + col + 3] + bias[col0 + col + 3];
            if (EPI == 0) {
                float4 o = make_float4(v0, v1, v2, v3);
                *(float4*)((float*)Cout + (size_t)(row0 + row) * Np + col0 + col) = o;
            } else {
                v0 = tanhf(v0); v1 = tanhf(v1); v2 = tanhf(v2); v3 = tanhf(v3);
                __nv_bfloat162 t0 = __floats2bfloat162_rn(v0, v1);
                __nv_bfloat162 t1 = __floats2bfloat162_rn(v2, v3);
                uint2 o = make_uint2(*(uint32_t*)&t0, *(uint32_t*)&t1);
                *(uint2*)((bf16*)Cout + (size_t)(row0 + row) * Np + col0 + col) = o;
            }
        }
    }
}

// ---------------- weight transpose+convert ----------------------------------
__global__ void transpose_w(const float* __restrict__ src, bf16* __restrict__ dst,
                            int Ks, int Ns, int Kd, int n_off) {
    __shared__ float tile[32][33];
    int k0 = blockIdx.x * 32, n0 = blockIdx.y * 32;
    for (int i = threadIdx.y; i < 32; i += 8)
        tile[i][threadIdx.x] = src[(size_t)(k0 + i) * Ns + n0 + threadIdx.x];
    __syncthreads();
    for (int i = threadIdx.y; i < 32; i += 8)
        dst[(size_t)(n_off + n0 + i) * Kd + k0 + threadIdx.x] =
            __float2bfloat16(tile[threadIdx.x][i]);
}

__global__ void concat_bias(const float* __restrict__ a, const float* __restrict__ b,
                            float* __restrict__ d, int n) {
    int i = blockIdx.x * blockDim.x + threadIdx.x;
    if (i < n) d[i] = a[i];
    else if (i < 2 * n) d[i] = b[i - n];
}

__global__ void conv_x(const float* __restrict__ x, bf16* __restrict__ xb) {
    size_t i = ((size_t)blockIdx.x * blockDim.x + threadIdx.x) * 8;
    float4 a = *(const float4*)(x + i);
    float4 b = *(const float4*)(x + i + 4);
    uint32_t p[4];
    __nv_bfloat162 t;
    t = __floats2bfloat162_rn(a.x, a.y); p[0] = *(uint32_t*)&t;
    t = __floats2bfloat162_rn(a.z, a.w); p[1] = *(uint32_t*)&t;
    t = __floats2bfloat162_rn(b.x, b.y); p[2] = *(uint32_t*)&t;
    t = __floats2bfloat162_rn(b.z, b.w); p[3] = *(uint32_t*)&t;
    *(uint4*)(xb + i) = *(uint4*)p;
}

// ---------------- per-row softmax + likelihood ------------------------------
__global__ void row_loss(const float* __restrict__ out4, const float* __restrict__ x,
                         const float* __restrict__ kl, float* __restrict__ rowout) {
    const int row = blockIdx.x;
    const int t = threadIdx.x;
    __shared__ float sh[8];
    const float* lr = out4 + (size_t)row * (2 * DIN);
    const float* vr = lr + DIN;
    float l0 = lr[t], l1 = lr[t + 256];

    float m = fmaxf(l0, l1);
#pragma unroll
    for (int o = 16; o > 0; o >>= 1) m = fmaxf(m, __shfl_xor_sync(0xffffffffu, m, o));
    if ((t & 31) == 0) sh[t >> 5] = m;
    __syncthreads();
    m = sh[0];
#pragma unroll
    for (int w = 1; w < 8; w++) m = fmaxf(m, sh[w]);
    __syncthreads();

    float e0 = expf(l0 - m), e1 = expf(l1 - m);
    float s = e0 + e1;
#pragma unroll
    for (int o = 16; o > 0; o >>= 1) s += __shfl_xor_sync(0xffffffffu, s, o);
    if ((t & 31) == 0) sh[t >> 5] = s;
    __syncthreads();
    s = 0.0f;
#pragma unroll
    for (int w = 0; w < 8; w++) s += sh[w];
    __syncthreads();
    float inv = 1.0f / s;

    const float* xr = x + (size_t)row * DIN;
    float acc = 0.0f;
    {
        float p = e0 * inv, xv = xr[t], lv = vr[t];
        float d = xv - p;
        acc += lv + d * d * expf(-lv);
        p = e1 * inv; xv = xr[t + 256]; lv = vr[t + 256];
        d = xv - p;
        acc += lv + d * d * expf(-lv);
    }
#pragma unroll
    for (int o = 16; o > 0; o >>= 1) acc += __shfl_xor_sync(0xffffffffu, acc, o);
    if ((t & 31) == 0) sh[t >> 5] = acc;
    __syncthreads();
    if (t == 0) {
        float tot = 0.0f;
#pragma unroll
        for (int w = 0; w < 8; w++) tot += sh[w];
        float ln_pxz = -0.5f * (tot + (float)DIN * LOG2PI);
        rowout[row] = ln_pxz - kl[row];
    }
}

__global__ void reduce_partial(const float* __restrict__ in, float* __restrict__ part) {
    const int t = threadIdx.x;
    __shared__ float sh[8];
    float v = in[blockIdx.x * 256 + t];
#pragma unroll
    for (int o = 16; o > 0; o >>= 1) v += __shfl_xor_sync(0xffffffffu, v, o);
    if ((t & 31) == 0) sh[t >> 5] = v;
    __syncthreads();
    if (t == 0) {
        float s = 0.0f;
#pragma unroll
        for (int w = 0; w < 8; w++) s += sh[w];
        part[blockIdx.x] = s;
    }
}
__global__ void reduce_final(const float* __restrict__ part, float* __restrict__ out) {
    const int t = threadIdx.x;
    __shared__ float sh[8];
    float v = part[t];
#pragma unroll
    for (int o = 16; o > 0; o >>= 1) v += __shfl_xor_sync(0xffffffffu, v, o);
    if ((t & 31) == 0) sh[t >> 5] = v;
    __syncthreads();
    if (t == 0) {
        float s = 0.0f;
#pragma unroll
        for (int w = 0; w < 8; w++) s += sh[w];
        out[0] = s * (1.0f / (float)BATCH);
    }
}

// ---------------- launch ----------------------------------------------------
extern "C" void kernel_launch(void* const* d_in, const int* in_sizes, int n_in,
                              void* d_out, int out_size) {
    const float* x        = (const float*)d_in[0];
    const float* eps      = (const float*)d_in[1];
    const float* W_enc_h  = (const float*)d_in[2];
    const float* b_enc_h  = (const float*)d_in[3];
    const float* W_enc_mu = (const float*)d_in[4];
    const float* b_enc_mu = (const float*)d_in[5];
    const float* W_enc_lv = (const float*)d_in[6];
    const float* b_enc_lv = (const float*)d_in[7];
    const float* W_dec_h  = (const float*)d_in[8];
    const float* b_dec_h  = (const float*)d_in[9];
    const float* W_dec_mu = (const float*)d_in[10];
    const float* b_dec_mu = (const float*)d_in[11];
    const float* W_dec_lv = (const float*)d_in[12];
    const float* b_dec_lv = (const float*)d_in[13];
    float* out = (float*)d_out;

    bf16 *p_xb, *p_h, *p_z, *p_Wt1, *p_Wt2, *p_Wt3, *p_Wt4;
    float *p_out4, *p_kl, *p_row, *p_part, *p_b2, *p_b4;
    cudaGetSymbolAddress((void**)&p_xb, sc_xb);
    cudaGetSymbolAddress((void**)&p_h, sc_h);
    cudaGetSymbolAddress((void**)&p_z, sc_z);
    cudaGetSymbolAddress((void**)&p_out4, sc_out4);
    cudaGetSymbolAddress((void**)&p_kl, sc_kl);
    cudaGetSymbolAddress((void**)&p_row, sc_row);
    cudaGetSymbolAddress((void**)&p_part, sc_part);
    cudaGetSymbolAddress((void**)&p_Wt1, sc_Wt1);
    cudaGetSymbolAddress((void**)&p_Wt2, sc_Wt2);
    cudaGetSymbolAddress((void**)&p_Wt3, sc_Wt3);
    cudaGetSymbolAddress((void**)&p_Wt4, sc_Wt4);
    cudaGetSymbolAddress((void**)&p_b2, sc_b2);
    cudaGetSymbolAddress((void**)&p_b4, sc_b4);

    cudaFuncSetAttribute(gemm_mma<0>, cudaFuncAttributeMaxDynamicSharedMemorySize, SMEMSZ);
    cudaFuncSetAttribute(gemm_mma<1>, cudaFuncAttributeMaxDynamicSharedMemorySize, SMEMSZ);
    cudaFuncSetAttribute(gemm_mma<2>, cudaFuncAttributeMaxDynamicSharedMemorySize, SMEMSZ);

    // prep
    conv_x<<<(BATCH * DIN) / (256 * 8), 256>>>(x, p_xb);
    transpose_w<<<dim3(16, 32), dim3(32, 8)>>>(W_enc_h,  p_Wt1, 512, 1024, 512, 0);
    transpose_w<<<dim3(32, 2),  dim3(32, 8)>>>(W_enc_mu, p_Wt2, 1024, 64, 1024, 0);
    transpose_w<<<dim3(32, 2),  dim3(32, 8)>>>(W_enc_lv, p_Wt2, 1024, 64, 1024, 64);
    transpose_w<<<dim3(2, 32),  dim3(32, 8)>>>(W_dec_h,  p_Wt3, 64, 1024, 64, 0);
    transpose_w<<<dim3(32, 16), dim3(32, 8)>>>(W_dec_mu, p_Wt4, 1024, 512, 1024, 0);
    transpose_w<<<dim3(32, 16), dim3(32, 8)>>>(W_dec_lv, p_Wt4, 1024, 512, 1024, 512);
    concat_bias<<<1, 128>>>(b_enc_mu, b_enc_lv, p_b2, LAT);
    concat_bias<<<4, 256>>>(b_dec_mu, b_dec_lv, p_b4, DIN);

    // 1) h = tanh(x @ W1)
    gemm_mma<1><<<dim3(8, 512), 256, SMEMSZ>>>(p_xb, DIN, p_Wt1, b_enc_h, p_h, HID,
                                               nullptr, nullptr, nullptr);
    // 2) enc head -> z, kl
    gemm_mma<2><<<dim3(1, 512), 256, SMEMSZ>>>(p_h, HID, p_Wt2, p_b2, nullptr, 0,
                                               eps, p_z, p_kl);
    // 3) hd = tanh(z @ W3)
    gemm_mma<1><<<dim3(8, 512), 256, SMEMSZ>>>(p_z, LAT, p_Wt3, b_dec_h, p_h, HID,
                                               nullptr, nullptr, nullptr);
    // 4) logits|lvx = hd @ W4
    gemm_mma<0><<<dim3(8, 512), 256, SMEMSZ>>>(p_h, HID, p_Wt4, p_b4, p_out4, 2 * DIN,
                                               nullptr, nullptr, nullptr);
    // 5) per-row loss, 6) deterministic mean
    row_loss<<<BATCH, 256>>>(p_out4, x, p_kl, p_row);
    reduce_partial<<<256, 256>>>(p_row, p_part);
    reduce_final<<<1, 256>>>(p_part, out);
}